// round 14
// baseline (speedup 1.0000x reference)
#include <cuda_runtime.h>
#include <cuda_bf16.h>
#include <cuda_fp16.h>
#include <math.h>
#include <stdint.h>

// Problem constants
#define NB   4
#define NT   512
#define NH   512
#define NV   32000
#define NS   512
#define NSDV 300
#define NTDV 512
#define MM   (NB*NT)              // 2048 rows
#define NOUT (NV+NSDV+NTDV)       // 32812
#define KK   (3*NH)               // 1536 expanded K (Ah|Ah|Al x Bh|Bl|Bh)

#define NBN      250              // N-tile CTAs per M-block
#define NSLICES  32               // finalize slices per M-block
#define RPS      4                // rows per slice (128/32)

// Scratch (static device arrays; no allocation allowed)
__device__ __half g_scoresh[(size_t)MM*NV];       // 131 MB (fp16 scores)
__device__ float g_p[MM*3];
__device__ float g_sumexp[MM];
__device__ unsigned long long g_amax[MM];         // packed exact vocab argmax
__device__ int   g_cnt[16];                       // per-M-block arrival counter
__device__ int   g_src_idx[NB*NS];
__device__ int   g_tgt_idx[NB*NT];
__device__ __nv_bfloat16 g_Ap[(size_t)MM*KK];     // 6.3 MB  [m][k']
__device__ __nv_bfloat16 g_Bp[(size_t)NV*KK];     // 98 MB   [n][k'] (K-major)

// ---------------------------------------------------------------------------
__device__ __forceinline__ uint32_t smem_u32(const void* p) {
    uint32_t a;
    asm("{ .reg .u64 t; cvta.to.shared.u64 t, %1; cvt.u32.u64 %0, t; }"
        : "=r"(a) : "l"(p));
    return a;
}
__device__ __forceinline__ void cp_async16(uint32_t dst, const void* src) {
    asm volatile("cp.async.cg.shared.global [%0], [%1], 16;"
                 :: "r"(dst), "l"(src));
}
#define CP_COMMIT() asm volatile("cp.async.commit_group;")
#define CP_WAIT1()  asm volatile("cp.async.wait_group 1;")

__device__ __forceinline__ void ldmx4(uint32_t* r, uint32_t addr) {
    asm volatile("ldmatrix.sync.aligned.m8n8.x4.shared.b16 {%0,%1,%2,%3}, [%4];"
                 : "=r"(r[0]), "=r"(r[1]), "=r"(r[2]), "=r"(r[3]) : "r"(addr));
}
__device__ __forceinline__ void mma16816(float* c, const uint32_t* a,
                                         const uint32_t* b) {
    asm volatile(
        "mma.sync.aligned.m16n8k16.row.col.f32.bf16.bf16.f32 "
        "{%0,%1,%2,%3}, {%4,%5,%6,%7}, {%8,%9}, {%0,%1,%2,%3};"
        : "+f"(c[0]), "+f"(c[1]), "+f"(c[2]), "+f"(c[3])
        : "r"(a[0]), "r"(a[1]), "r"(a[2]), "r"(a[3]), "r"(b[0]), "r"(b[1]));
}

// order-preserving float -> uint key
__device__ __forceinline__ uint32_t fkey(float v) {
    uint32_t b = __float_as_uint(v);
    return b ^ ((b & 0x80000000u) ? 0xFFFFFFFFu : 0x80000000u);
}
__device__ __forceinline__ float unfkey(uint32_t k) {
    uint32_t b = (k & 0x80000000u) ? (k ^ 0x80000000u) : ~k;
    return __uint_as_float(b);
}

// ---------------------------------------------------------------------------
// One-hot index extraction
// ---------------------------------------------------------------------------
__global__ void prep_idx_kernel(const float* __restrict__ smap,
                                const float* __restrict__ tmap) {
    int i = blockIdx.x * blockDim.x + threadIdx.x;   // 0..2047
    if (i >= NB*NS) return;
    {
        const float* r = smap + (size_t)i * NSDV;
        int idx = 0;
        for (int v = 0; v < NSDV; v++) if (r[v] > 0.5f) idx = v;
        g_src_idx[i] = idx;
    }
    {
        const float* r = tmap + (size_t)i * NTDV;
        int idx = 0;
        for (int v = 0; v < NTDV; v++) if (r[v] > 0.5f) idx = v;
        g_tgt_idx[i] = idx;
    }
}

// ---------------------------------------------------------------------------
// Merged: 3-way gate p = softmax(h@Wp+bp), A' = [Ah|Ah|Al] build,
// zero g_sumexp / g_amax / g_cnt. One warp per row.
// ---------------------------------------------------------------------------
__global__ void p_conv_kernel(const float* __restrict__ H,
                              const float* __restrict__ Wp,
                              const float* __restrict__ bp) {
    int warp = threadIdx.x >> 5;
    int lane = threadIdx.x & 31;
    int row  = blockIdx.x * 4 + warp;
    if (row >= MM) return;
    const float* h = H + (size_t)row * NH;
    __nv_bfloat16* ap = g_Ap + (size_t)row * KK;
    float s0 = 0.f, s1 = 0.f, s2 = 0.f;
    #pragma unroll
    for (int k = lane; k < NH; k += 32) {
        float hv = h[k];
        __nv_bfloat16 hi = __float2bfloat16(hv);
        __nv_bfloat16 lo = __float2bfloat16(hv - __bfloat162float(hi));
        ap[k]        = hi;
        ap[k + NH]   = hi;
        ap[k + 2*NH] = lo;
        s0 = fmaf(hv, Wp[k*3+0], s0);
        s1 = fmaf(hv, Wp[k*3+1], s1);
        s2 = fmaf(hv, Wp[k*3+2], s2);
    }
    #pragma unroll
    for (int o = 16; o > 0; o >>= 1) {
        s0 += __shfl_down_sync(0xffffffff, s0, o);
        s1 += __shfl_down_sync(0xffffffff, s1, o);
        s2 += __shfl_down_sync(0xffffffff, s2, o);
    }
    if (lane == 0) {
        g_sumexp[row] = 0.f;
        g_amax[row]   = 0ull;
        if (row < 16) g_cnt[row] = 0;
        s0 += bp[0]; s1 += bp[1]; s2 += bp[2];
        float m = fmaxf(s0, fmaxf(s1, s2));
        float e0 = expf(s0 - m), e1 = expf(s1 - m), e2 = expf(s2 - m);
        float inv = 1.0f / (e0 + e1 + e2);
        g_p[row*3+0] = e0 * inv;
        g_p[row*3+1] = e1 * inv;
        g_p[row*3+2] = e2 * inv;
    }
}

// ---------------------------------------------------------------------------
// Transpose Wv [NH][NV] -> B' [NV][K'] = [Bh | Bl | Bh]
// ---------------------------------------------------------------------------
__global__ void convB_kernel(const float* __restrict__ Wv) {
    __shared__ float t[32][33];
    int n0 = blockIdx.x * 32, k0 = blockIdx.y * 32;
    int tx = threadIdx.x, ty = threadIdx.y;   // block (32, 8)
    #pragma unroll
    for (int i = 0; i < 32; i += 8)
        t[ty+i][tx] = Wv[(size_t)(k0 + ty + i) * NV + n0 + tx];   // t[k][n]
    __syncthreads();
    #pragma unroll
    for (int i = 0; i < 32; i += 8) {
        float v = t[tx][ty+i];                 // k = k0+tx, n = n0+ty+i
        __nv_bfloat16 hi = __float2bfloat16(v);
        __nv_bfloat16 lo = __float2bfloat16(v - __bfloat162float(hi));
        size_t base = (size_t)(n0 + ty + i) * KK + k0 + tx;
        g_Bp[base]        = hi;
        g_Bp[base + NH]   = lo;
        g_Bp[base + 2*NH] = hi;
    }
}

// ---------------------------------------------------------------------------
// Fused GEMM + finalize. GEMM: R7 config (128x128, BK=64, 3-stage, 8 warps
// of 32x64). Epilogue: fp16 scores + sumexp + exact vocab argmax. Then the
// last NSLICES arrivals per M-block finalize RPS rows each (prob streaming
// from L2-hot scores, copy scatter, prediction).
// ---------------------------------------------------------------------------
#define BM 128
#define BN 128
#define BK 64
#define NKITER (KK/BK)        // 24
#define STAGE_B 32768         // A tile 16KB + B tile 16KB
#define SMEM_GEMM (3*STAGE_B) // 96 KB

__global__ __launch_bounds__(256, 2)
void gemm_mma_kernel(const float* __restrict__ bias,
                     const float* __restrict__ satt,
                     const float* __restrict__ tatt,
                     float* __restrict__ out) {
    extern __shared__ char smem[];
    const uint32_t sb = smem_u32(smem);
    const int tid  = threadIdx.x;
    const int w    = tid >> 5;
    const int lane = tid & 31;
    const int bm   = blockIdx.y * BM;    // 16
    const int bn   = blockIdx.x * BN;    // 250
    const int wm   = w & 3;              // warp row (4)
    const int wn   = w >> 2;             // warp col (2)

    float acc[2][8][4];
    #pragma unroll
    for (int i = 0; i < 2; i++)
        #pragma unroll
        for (int j = 0; j < 8; j++)
            #pragma unroll
            for (int q = 0; q < 4; q++) acc[i][j][q] = 0.f;

    // --- strength-reduced loader state ---
    const int lr = tid >> 3;             // 0..31
    const int lc = tid & 7;              // 16B chunk
    const __nv_bfloat16* aptr = g_Ap + (size_t)(bm + lr) * KK + lc * 8;
    const __nv_bfloat16* bptr = g_Bp + (size_t)(bn + lr) * KK + lc * 8;
    const uint32_t sw0 = (uint32_t)lr * 128 + (uint32_t)((lc ^ (lr & 7)) * 16);

#define LOAD_STAGE(s) do {                                                      \
    uint32_t d = sb + (uint32_t)(s) * STAGE_B + sw0;                            \
    _Pragma("unroll")                                                           \
    for (int i = 0; i < 4; i++) {                                               \
        cp_async16(d + i * 4096,         aptr + (size_t)i * 32 * KK);           \
        cp_async16(d + 16384 + i * 4096, bptr + (size_t)i * 32 * KK);           \
    }                                                                           \
    CP_COMMIT();                                                                \
    aptr += BK; bptr += BK;                                                     \
} while (0)

    // --- strength-reduced ldmatrix bases ---
    const uint32_t lnx = (uint32_t)(lane >> 4) * 16;
    uint32_t rp_a[2], rp_b[4];
    #pragma unroll
    for (int i = 0; i < 2; i++) {
        int row = wm * 32 + i * 16 + (lane & 15);
        rp_a[i] = (uint32_t)row * 128 + (lnx ^ (uint32_t)((row & 7) * 16));
    }
    #pragma unroll
    for (int jj = 0; jj < 4; jj++) {
        int row = wn * 64 + jj * 16 + (lane & 15);
        rp_b[jj] = (uint32_t)row * 128 + (lnx ^ (uint32_t)((row & 7) * 16));
    }

    LOAD_STAGE(0);
    LOAD_STAGE(1);

    for (int kt = 0; kt < NKITER; kt++) {
        const int s = kt % 3;
        CP_WAIT1();
        __syncthreads();
        if (kt + 2 < NKITER) LOAD_STAGE((kt + 2) % 3);

        const uint32_t abase = sb + (uint32_t)s * STAGE_B;
        const uint32_t bbase = abase + 16384;
        #pragma unroll
        for (int ks = 0; ks < 4; ks++) {
            const uint32_t kx = (uint32_t)ks << 5;
            uint32_t a[2][4];
            #pragma unroll
            for (int i = 0; i < 2; i++)
                ldmx4(a[i], abase + (rp_a[i] ^ kx));
            uint32_t b[8][2];
            #pragma unroll
            for (int jj = 0; jj < 4; jj++) {
                uint32_t r[4];
                ldmx4(r, bbase + (rp_b[jj] ^ kx));
                b[2*jj][0]   = r[0]; b[2*jj][1]   = r[2];
                b[2*jj+1][0] = r[1]; b[2*jj+1][1] = r[3];
            }
            #pragma unroll
            for (int i = 0; i < 2; i++)
                #pragma unroll
                for (int j = 0; j < 8; j++)
                    mma16816(acc[i][j], a[i], b[j]);
        }
    }

    // epilogue: bias add, fp16 store, per-row sumexp + exact vocab argmax
    #pragma unroll
    for (int i = 0; i < 2; i++) {
        const int row = bm + wm * 32 + i * 16 + (lane >> 2);
        float s0 = 0.f, s1 = 0.f;
        float m0 = -INFINITY, m1 = -INFINITY;
        int   c0 = 1, c1 = 1;
        #pragma unroll
        for (int j = 0; j < 8; j++) {
            const int col = bn + wn * 64 + j * 8 + (lane & 3) * 2;
            const float b0 = bias[col], b1 = bias[col + 1];
            float v00 = acc[i][j][0] + b0, v01 = acc[i][j][1] + b1;
            float v10 = acc[i][j][2] + b0, v11 = acc[i][j][3] + b1;
            *(__half2*)(g_scoresh + (size_t)row * NV + col)
                = __floats2half2_rn(v00, v01);
            *(__half2*)(g_scoresh + (size_t)(row + 8) * NV + col)
                = __floats2half2_rn(v10, v11);
            bool nz = (col != 0);
            s0 += (nz ? __expf(v00) : 0.f) + __expf(v01);
            s1 += (nz ? __expf(v10) : 0.f) + __expf(v11);
            if (nz && v00 > m0) { m0 = v00; c0 = col; }
            if (v01 > m0)       { m0 = v01; c0 = col + 1; }
            if (nz && v10 > m1) { m1 = v10; c1 = col; }
            if (v11 > m1)       { m1 = v11; c1 = col + 1; }
        }
        #pragma unroll
        for (int o = 1; o <= 2; o <<= 1) {
            s0 += __shfl_xor_sync(0xffffffff, s0, o);
            s1 += __shfl_xor_sync(0xffffffff, s1, o);
            float mo0 = __shfl_xor_sync(0xffffffff, m0, o);
            int   co0 = __shfl_xor_sync(0xffffffff, c0, o);
            if (mo0 > m0 || (mo0 == m0 && co0 < c0)) { m0 = mo0; c0 = co0; }
            float mo1 = __shfl_xor_sync(0xffffffff, m1, o);
            int   co1 = __shfl_xor_sync(0xffffffff, c1, o);
            if (mo1 > m1 || (mo1 == m1 && co1 < c1)) { m1 = mo1; c1 = co1; }
        }
        if ((lane & 3) == 0) {
            atomicAdd(&g_sumexp[row],     s0);
            atomicAdd(&g_sumexp[row + 8], s1);
            unsigned long long p0 =
                ((unsigned long long)fkey(m0) << 32)
                | (unsigned long long)(0xFFFFFFFFu - (uint32_t)c0);
            unsigned long long p1 =
                ((unsigned long long)fkey(m1) << 32)
                | (unsigned long long)(0xFFFFFFFFu - (uint32_t)c1);
            atomicMax(&g_amax[row],     p0);
            atomicMax(&g_amax[row + 8], p1);
        }
    }

    // ---- post-completion fused finalize ----
    __threadfence();
    __shared__ int s_d;
    __syncthreads();                 // all epilogue atomics issued
    if (tid == 0) s_d = atomicAdd(&g_cnt[blockIdx.y], 1);
    __syncthreads();
    const int d = s_d;
    if (d < NBN - NSLICES) return;   // not a finalizer CTA

    // wait until the whole M-block is done
    if (tid == 0) {
        volatile int* vc = &g_cnt[blockIdx.y];
        while (*vc < NBN) __nanosleep(64);
    }
    __syncthreads();
    __threadfence();                 // order subsequent reads

    const int slice = d - (NBN - NSLICES);
    const int r0    = bm + slice * RPS;
    const int b     = r0 / NT;       // batch constant across the 4 rows

    // smem reuse for copy-region scatter + reductions
    float* src_acc = (float*)(smem);                 // 300 floats
    float* tgt_acc = (float*)(smem + 2048);          // 512 floats
    float* red     = (float*)(smem + 8192);          // 256
    int*   redi    = (int*)  (smem + 8192 + 1024);   // 256

    for (int rr = 0; rr < RPS; rr++) {
        const int row = r0 + rr;
        const float pg    = g_p[row*3+2];
        const float pcs   = g_p[row*3+0];
        const float pct   = g_p[row*3+1];
        const float scale = pg / g_sumexp[row];
        float* orow = out + (size_t)row * NOUT;

        // vocab probs: stream fp16 scores -> f32 probs
        const uint4* s4 = (const uint4*)(g_scoresh + (size_t)row * NV);
        float4* orow4 = (float4*)orow;
        for (int i2 = tid; i2 < NV/8; i2 += 256) {
            uint4 u = __ldcs(&s4[i2]);
            float2 a0 = __half22float2(*(__half2*)&u.x);
            float2 a1 = __half22float2(*(__half2*)&u.y);
            float2 a2 = __half22float2(*(__half2*)&u.z);
            float2 a3 = __half22float2(*(__half2*)&u.w);
            float4 p0, p1;
            p0.x = __expf(a0.x) * scale;  p0.y = __expf(a0.y) * scale;
            p0.z = __expf(a1.x) * scale;  p0.w = __expf(a1.y) * scale;
            p1.x = __expf(a2.x) * scale;  p1.y = __expf(a2.y) * scale;
            p1.z = __expf(a3.x) * scale;  p1.w = __expf(a3.y) * scale;
            if (i2 == 0) p0.x = 0.f;
            __stcs(&orow4[2*i2],     p0);
            __stcs(&orow4[2*i2 + 1], p1);
        }

        // copy regions
        for (int i2 = tid; i2 < NSDV; i2 += 256) src_acc[i2] = 0.f;
        for (int i2 = tid; i2 < NTDV; i2 += 256) tgt_acc[i2] = 0.f;
        __syncthreads();
        for (int s2 = tid; s2 < NS; s2 += 256)
            atomicAdd(&src_acc[g_src_idx[b*NS + s2]], satt[(size_t)row*NS + s2]);
        for (int n2 = tid; n2 < NT; n2 += 256)
            atomicAdd(&tgt_acc[g_tgt_idx[b*NT + n2]], tatt[(size_t)row*NTDV + n2]);
        __syncthreads();

        float bmax = -1.f;
        int   bidx = NOUT;
        for (int v = tid; v < NSDV; v += 256) {
            float pv = pcs * src_acc[v];
            __stcs(&orow[NV + v], pv);
            int gi = NV + v;
            if (pv > bmax || (pv == bmax && gi < bidx)) { bmax = pv; bidx = gi; }
        }
        for (int v = tid; v < NTDV; v += 256) {
            float pv = pct * tgt_acc[v];
            __stcs(&orow[NV + NSDV + v], pv);
            int gi = NV + NSDV + v;
            if (pv > bmax || (pv == bmax && gi < bidx)) { bmax = pv; bidx = gi; }
        }
        red[tid]  = bmax;
        redi[tid] = bidx;
        __syncthreads();
        for (int o = 128; o > 0; o >>= 1) {
            if (tid < o) {
                float v2 = red[tid + o]; int i3 = redi[tid + o];
                if (v2 > red[tid] || (v2 == red[tid] && i3 < redi[tid])) {
                    red[tid] = v2; redi[tid] = i3;
                }
            }
            __syncthreads();
        }
        if (tid == 0) {
            unsigned long long pk = g_amax[row];
            float vmax = __expf(unfkey((uint32_t)(pk >> 32))) * scale;
            int   vidx = (int)(0xFFFFFFFFu - (uint32_t)pk);
            float cmax = red[0];
            int   cidx = redi[0];
            int   pred = (cmax > vmax || (cmax == vmax && cidx < vidx))
                           ? cidx : vidx;
            out[(size_t)MM * NOUT + row] = (float)pred;
        }
        __syncthreads();
    }
}

// ---------------------------------------------------------------------------
extern "C" void kernel_launch(void* const* d_in, const int* in_sizes, int n_in,
                              void* d_out, int out_size) {
    const float* hiddens = (const float*)d_in[0];
    const float* Wp      = (const float*)d_in[1];
    const float* bp      = (const float*)d_in[2];
    const float* Wv      = (const float*)d_in[3];
    const float* bv      = (const float*)d_in[4];
    const float* satt    = (const float*)d_in[5];
    const float* smap    = (const float*)d_in[6];
    const float* tatt    = (const float*)d_in[7];
    const float* tmap    = (const float*)d_in[8];
    float* out = (float*)d_out;

    cudaFuncSetAttribute(gemm_mma_kernel,
                         cudaFuncAttributeMaxDynamicSharedMemorySize, SMEM_GEMM);

    // gemm in launch slot 4 -> gets ncu-captured
    convB_kernel<<<dim3(NV/32, NH/32), dim3(32, 8)>>>(Wv);       // 1
    p_conv_kernel<<<MM/4, 128>>>(hiddens, Wp, bp);               // 2
    prep_idx_kernel<<<8, 256>>>(smap, tmap);                     // 3
    gemm_mma_kernel<<<dim3(NBN, MM/BM), 256, SMEM_GEMM>>>(
        bv, satt, tatt, out);                                    // 4
}

// round 15
// speedup vs baseline: 1.2095x; 1.2095x over previous
#include <cuda_runtime.h>
#include <cuda_bf16.h>
#include <cuda_fp16.h>
#include <math.h>
#include <stdint.h>

// Problem constants
#define NB   4
#define NT   512
#define NH   512
#define NV   32000
#define NS   512
#define NSDV 300
#define NTDV 512
#define MM   (NB*NT)              // 2048 rows
#define NOUT (NV+NSDV+NTDV)       // 32812
#define KK   (3*NH)               // 1536 expanded K (Ah|Ah|Al x Bh|Bl|Bh)

// Scratch (static device arrays; no allocation allowed)
__device__ __half g_scoresh[(size_t)MM*NV];       // 131 MB (fp16 scores)
__device__ float g_p[MM*3];
__device__ float g_sumexp[MM];
__device__ unsigned long long g_amax[MM];         // packed exact vocab argmax
__device__ int   g_src_idx[NB*NS];
__device__ int   g_tgt_idx[NB*NT];
__device__ __nv_bfloat16 g_Ap[(size_t)MM*KK];     // 6.3 MB  [m][k']
__device__ __nv_bfloat16 g_Bp[(size_t)NV*KK];     // 98 MB   [n][k'] (K-major)

// ---------------------------------------------------------------------------
__device__ __forceinline__ uint32_t smem_u32(const void* p) {
    uint32_t a;
    asm("{ .reg .u64 t; cvta.to.shared.u64 t, %1; cvt.u32.u64 %0, t; }"
        : "=r"(a) : "l"(p));
    return a;
}
__device__ __forceinline__ void cp_async16(uint32_t dst, const void* src) {
    asm volatile("cp.async.cg.shared.global [%0], [%1], 16;"
                 :: "r"(dst), "l"(src));
}
#define CP_COMMIT() asm volatile("cp.async.commit_group;")
#define CP_WAIT1()  asm volatile("cp.async.wait_group 1;")

__device__ __forceinline__ void ldmx4(uint32_t* r, uint32_t addr) {
    asm volatile("ldmatrix.sync.aligned.m8n8.x4.shared.b16 {%0,%1,%2,%3}, [%4];"
                 : "=r"(r[0]), "=r"(r[1]), "=r"(r[2]), "=r"(r[3]) : "r"(addr));
}
__device__ __forceinline__ void mma16816(float* c, const uint32_t* a,
                                         const uint32_t* b) {
    asm volatile(
        "mma.sync.aligned.m16n8k16.row.col.f32.bf16.bf16.f32 "
        "{%0,%1,%2,%3}, {%4,%5,%6,%7}, {%8,%9}, {%0,%1,%2,%3};"
        : "+f"(c[0]), "+f"(c[1]), "+f"(c[2]), "+f"(c[3])
        : "r"(a[0]), "r"(a[1]), "r"(a[2]), "r"(a[3]), "r"(b[0]), "r"(b[1]));
}

// order-preserving float -> uint key (works for all finite floats)
__device__ __forceinline__ uint32_t fkey(float v) {
    uint32_t b = __float_as_uint(v);
    return b ^ ((b & 0x80000000u) ? 0xFFFFFFFFu : 0x80000000u);
}
__device__ __forceinline__ float unfkey(uint32_t k) {
    uint32_t b = (k & 0x80000000u) ? (k ^ 0x80000000u) : ~k;
    return __uint_as_float(b);
}

// ---------------------------------------------------------------------------
// One-hot index extraction
// ---------------------------------------------------------------------------
__global__ void prep_idx_kernel(const float* __restrict__ smap,
                                const float* __restrict__ tmap) {
    int i = blockIdx.x * blockDim.x + threadIdx.x;   // 0..2047
    if (i >= NB*NS) return;
    {
        const float* r = smap + (size_t)i * NSDV;
        int idx = 0;
        for (int v = 0; v < NSDV; v++) if (r[v] > 0.5f) idx = v;
        g_src_idx[i] = idx;
    }
    {
        const float* r = tmap + (size_t)i * NTDV;
        int idx = 0;
        for (int v = 0; v < NTDV; v++) if (r[v] > 0.5f) idx = v;
        g_tgt_idx[i] = idx;
    }
}

// ---------------------------------------------------------------------------
// Merged: 3-way gate p = softmax(h@Wp+bp), A' = [Ah|Ah|Al] build,
// zero g_sumexp / g_amax. One warp per row.
// ---------------------------------------------------------------------------
__global__ void p_conv_kernel(const float* __restrict__ H,
                              const float* __restrict__ Wp,
                              const float* __restrict__ bp) {
    int warp = threadIdx.x >> 5;
    int lane = threadIdx.x & 31;
    int row  = blockIdx.x * 4 + warp;
    if (row >= MM) return;
    const float* h = H + (size_t)row * NH;
    __nv_bfloat16* ap = g_Ap + (size_t)row * KK;
    float s0 = 0.f, s1 = 0.f, s2 = 0.f;
    #pragma unroll
    for (int k = lane; k < NH; k += 32) {
        float hv = h[k];
        __nv_bfloat16 hi = __float2bfloat16(hv);
        __nv_bfloat16 lo = __float2bfloat16(hv - __bfloat162float(hi));
        ap[k]        = hi;
        ap[k + NH]   = hi;
        ap[k + 2*NH] = lo;
        s0 = fmaf(hv, Wp[k*3+0], s0);
        s1 = fmaf(hv, Wp[k*3+1], s1);
        s2 = fmaf(hv, Wp[k*3+2], s2);
    }
    #pragma unroll
    for (int o = 16; o > 0; o >>= 1) {
        s0 += __shfl_down_sync(0xffffffff, s0, o);
        s1 += __shfl_down_sync(0xffffffff, s1, o);
        s2 += __shfl_down_sync(0xffffffff, s2, o);
    }
    if (lane == 0) {
        g_sumexp[row] = 0.f;
        g_amax[row]   = 0ull;
        s0 += bp[0]; s1 += bp[1]; s2 += bp[2];
        float m = fmaxf(s0, fmaxf(s1, s2));
        float e0 = expf(s0 - m), e1 = expf(s1 - m), e2 = expf(s2 - m);
        float inv = 1.0f / (e0 + e1 + e2);
        g_p[row*3+0] = e0 * inv;
        g_p[row*3+1] = e1 * inv;
        g_p[row*3+2] = e2 * inv;
    }
}

// ---------------------------------------------------------------------------
// Transpose Wv [NH][NV] -> B' [NV][K'] = [Bh | Bl | Bh]
// ---------------------------------------------------------------------------
__global__ void convB_kernel(const float* __restrict__ Wv) {
    __shared__ float t[32][33];
    int n0 = blockIdx.x * 32, k0 = blockIdx.y * 32;
    int tx = threadIdx.x, ty = threadIdx.y;   // block (32, 8)
    #pragma unroll
    for (int i = 0; i < 32; i += 8)
        t[ty+i][tx] = Wv[(size_t)(k0 + ty + i) * NV + n0 + tx];   // t[k][n]
    __syncthreads();
    #pragma unroll
    for (int i = 0; i < 32; i += 8) {
        float v = t[tx][ty+i];                 // k = k0+tx, n = n0+ty+i
        __nv_bfloat16 hi = __float2bfloat16(v);
        __nv_bfloat16 lo = __float2bfloat16(v - __bfloat162float(hi));
        size_t base = (size_t)(n0 + ty + i) * KK + k0 + tx;
        g_Bp[base]        = hi;
        g_Bp[base + NH]   = lo;
        g_Bp[base + 2*NH] = hi;
    }
}

// ---------------------------------------------------------------------------
// mma.sync GEMM (R7 config): 128x128 tiles, BK=64, 3-stage cp.async,
// 8 warps of 32x64, strength-reduced addressing. Epilogue: fp16 score
// store + per-row sumexp + EXACT per-row vocab argmax (packed atomicMax).
// ---------------------------------------------------------------------------
#define BM 128
#define BN 128
#define BK 64
#define NKITER (KK/BK)        // 24
#define STAGE_B 32768         // A tile 16KB + B tile 16KB
#define SMEM_GEMM (3*STAGE_B) // 96 KB

__global__ __launch_bounds__(256, 2)
void gemm_mma_kernel(const float* __restrict__ bias) {
    extern __shared__ char smem[];
    const uint32_t sb = smem_u32(smem);
    const int tid  = threadIdx.x;
    const int w    = tid >> 5;
    const int lane = tid & 31;
    const int bm   = blockIdx.y * BM;    // 16
    const int bn   = blockIdx.x * BN;    // 250
    const int wm   = w & 3;              // warp row (4)
    const int wn   = w >> 2;             // warp col (2)

    float acc[2][8][4];
    #pragma unroll
    for (int i = 0; i < 2; i++)
        #pragma unroll
        for (int j = 0; j < 8; j++)
            #pragma unroll
            for (int q = 0; q < 4; q++) acc[i][j][q] = 0.f;

    // --- strength-reduced loader state ---
    const int lr = tid >> 3;             // 0..31
    const int lc = tid & 7;              // 16B chunk
    const __nv_bfloat16* aptr = g_Ap + (size_t)(bm + lr) * KK + lc * 8;
    const __nv_bfloat16* bptr = g_Bp + (size_t)(bn + lr) * KK + lc * 8;
    const uint32_t sw0 = (uint32_t)lr * 128 + (uint32_t)((lc ^ (lr & 7)) * 16);

#define LOAD_STAGE(s) do {                                                      \
    uint32_t d = sb + (uint32_t)(s) * STAGE_B + sw0;                            \
    _Pragma("unroll")                                                           \
    for (int i = 0; i < 4; i++) {                                               \
        cp_async16(d + i * 4096,         aptr + (size_t)i * 32 * KK);           \
        cp_async16(d + 16384 + i * 4096, bptr + (size_t)i * 32 * KK);           \
    }                                                                           \
    CP_COMMIT();                                                                \
    aptr += BK; bptr += BK;                                                     \
} while (0)

    // --- strength-reduced ldmatrix bases ---
    const uint32_t lnx = (uint32_t)(lane >> 4) * 16;
    uint32_t rp_a[2], rp_b[4];
    #pragma unroll
    for (int i = 0; i < 2; i++) {
        int row = wm * 32 + i * 16 + (lane & 15);
        rp_a[i] = (uint32_t)row * 128 + (lnx ^ (uint32_t)((row & 7) * 16));
    }
    #pragma unroll
    for (int jj = 0; jj < 4; jj++) {
        int row = wn * 64 + jj * 16 + (lane & 15);
        rp_b[jj] = (uint32_t)row * 128 + (lnx ^ (uint32_t)((row & 7) * 16));
    }

    LOAD_STAGE(0);
    LOAD_STAGE(1);

    for (int kt = 0; kt < NKITER; kt++) {
        const int s = kt % 3;
        CP_WAIT1();
        __syncthreads();
        if (kt + 2 < NKITER) LOAD_STAGE((kt + 2) % 3);

        const uint32_t abase = sb + (uint32_t)s * STAGE_B;
        const uint32_t bbase = abase + 16384;
        #pragma unroll
        for (int ks = 0; ks < 4; ks++) {
            const uint32_t kx = (uint32_t)ks << 5;
            uint32_t a[2][4];
            #pragma unroll
            for (int i = 0; i < 2; i++)
                ldmx4(a[i], abase + (rp_a[i] ^ kx));
            uint32_t b[8][2];
            #pragma unroll
            for (int jj = 0; jj < 4; jj++) {
                uint32_t r[4];
                ldmx4(r, bbase + (rp_b[jj] ^ kx));
                b[2*jj][0]   = r[0]; b[2*jj][1]   = r[2];
                b[2*jj+1][0] = r[1]; b[2*jj+1][1] = r[3];
            }
            #pragma unroll
            for (int i = 0; i < 2; i++)
                #pragma unroll
                for (int j = 0; j < 8; j++)
                    mma16816(acc[i][j], a[i], b[j]);
        }
    }

    // epilogue: bias add, fp16 store, per-row sumexp + exact vocab argmax
    #pragma unroll
    for (int i = 0; i < 2; i++) {
        const int row = bm + wm * 32 + i * 16 + (lane >> 2);
        float s0 = 0.f, s1 = 0.f;            // sumexp: rows row, row+8
        float m0 = -INFINITY, m1 = -INFINITY;
        int   c0 = 1, c1 = 1;
        #pragma unroll
        for (int j = 0; j < 8; j++) {
            const int col = bn + wn * 64 + j * 8 + (lane & 3) * 2;
            const float b0 = bias[col], b1 = bias[col + 1];
            float v00 = acc[i][j][0] + b0, v01 = acc[i][j][1] + b1;
            float v10 = acc[i][j][2] + b0, v11 = acc[i][j][3] + b1;
            *(__half2*)(g_scoresh + (size_t)row * NV + col)
                = __floats2half2_rn(v00, v01);
            *(__half2*)(g_scoresh + (size_t)(row + 8) * NV + col)
                = __floats2half2_rn(v10, v11);
            bool nz = (col != 0);
            s0 += (nz ? __expf(v00) : 0.f) + __expf(v01);
            s1 += (nz ? __expf(v10) : 0.f) + __expf(v11);
            if (nz && v00 > m0) { m0 = v00; c0 = col; }
            if (v01 > m0)       { m0 = v01; c0 = col + 1; }
            if (nz && v10 > m1) { m1 = v10; c1 = col; }
            if (v11 > m1)       { m1 = v11; c1 = col + 1; }
        }
        #pragma unroll
        for (int o = 1; o <= 2; o <<= 1) {
            s0 += __shfl_xor_sync(0xffffffff, s0, o);
            s1 += __shfl_xor_sync(0xffffffff, s1, o);
            float mo0 = __shfl_xor_sync(0xffffffff, m0, o);
            int   co0 = __shfl_xor_sync(0xffffffff, c0, o);
            if (mo0 > m0 || (mo0 == m0 && co0 < c0)) { m0 = mo0; c0 = co0; }
            float mo1 = __shfl_xor_sync(0xffffffff, m1, o);
            int   co1 = __shfl_xor_sync(0xffffffff, c1, o);
            if (mo1 > m1 || (mo1 == m1 && co1 < c1)) { m1 = mo1; c1 = co1; }
        }
        if ((lane & 3) == 0) {
            atomicAdd(&g_sumexp[row],     s0);
            atomicAdd(&g_sumexp[row + 8], s1);
            unsigned long long p0 =
                ((unsigned long long)fkey(m0) << 32)
                | (unsigned long long)(0xFFFFFFFFu - (uint32_t)c0);
            unsigned long long p1 =
                ((unsigned long long)fkey(m1) << 32)
                | (unsigned long long)(0xFFFFFFFFu - (uint32_t)c1);
            atomicMax(&g_amax[row],     p0);
            atomicMax(&g_amax[row + 8], p1);
        }
    }
}

// ---------------------------------------------------------------------------
// Finalize: grid (NQ+1, MM). q<NQ: pure-streaming vocab prob write from
// fp16 scores (no reductions/atomics -> fine-grained split is free).
// q==NQ: copy-region scatter + write + final argmax vs exact vocab max.
// ---------------------------------------------------------------------------
#define NQ 4
__global__ __launch_bounds__(256)
void finalize_kernel(const float* __restrict__ satt,
                     const float* __restrict__ tatt,
                     float* __restrict__ out) {
    const int row = blockIdx.y;
    const int q   = blockIdx.x;
    const int tid = threadIdx.x;

    const float pg    = g_p[row*3+2];
    const float scale = pg / g_sumexp[row];
    float* orow = out + (size_t)row * NOUT;

    if (q < NQ) {
        // vocab slice: 8 halves (16B) per iteration, pure streaming
        const uint4* s4 = (const uint4*)(g_scoresh + (size_t)row * NV);
        float4* orow4 = (float4*)orow;
        const int i0 = q * (NV/8/NQ);
        for (int i = i0 + tid; i < i0 + NV/8/NQ; i += 256) {
            uint4 u = __ldcs(&s4[i]);
            float2 a0 = __half22float2(*(__half2*)&u.x);
            float2 a1 = __half22float2(*(__half2*)&u.y);
            float2 a2 = __half22float2(*(__half2*)&u.z);
            float2 a3 = __half22float2(*(__half2*)&u.w);
            float4 p0, p1;
            p0.x = __expf(a0.x) * scale;  p0.y = __expf(a0.y) * scale;
            p0.z = __expf(a1.x) * scale;  p0.w = __expf(a1.y) * scale;
            p1.x = __expf(a2.x) * scale;  p1.y = __expf(a2.y) * scale;
            p1.z = __expf(a3.x) * scale;  p1.w = __expf(a3.y) * scale;
            if (i == 0) p0.x = 0.f;      // masked vocab index 0
            __stcs(&orow4[2*i],     p0);
            __stcs(&orow4[2*i + 1], p1);
        }
        return;
    }

    // copy-region block
    __shared__ float red[256];
    __shared__ int   redi[256];
    __shared__ float src_acc[NSDV];
    __shared__ float tgt_acc[NTDV];
    const int b = row / NT;
    const float pcs = g_p[row*3+0];
    const float pct = g_p[row*3+1];

    for (int i = tid; i < NSDV; i += 256) src_acc[i] = 0.f;
    for (int i = tid; i < NTDV; i += 256) tgt_acc[i] = 0.f;
    __syncthreads();
    for (int s = tid; s < NS; s += 256)
        atomicAdd(&src_acc[g_src_idx[b*NS + s]], satt[(size_t)row*NS + s]);
    for (int n = tid; n < NT; n += 256)
        atomicAdd(&tgt_acc[g_tgt_idx[b*NT + n]], tatt[(size_t)row*NTDV + n]);
    __syncthreads();

    float bmax = -1.f;
    int   bidx = NOUT;
    for (int v = tid; v < NSDV; v += 256) {
        float pv = pcs * src_acc[v];
        __stcs(&orow[NV + v], pv);
        int gi = NV + v;
        if (pv > bmax || (pv == bmax && gi < bidx)) { bmax = pv; bidx = gi; }
    }
    for (int v = tid; v < NTDV; v += 256) {
        float pv = pct * tgt_acc[v];
        __stcs(&orow[NV + NSDV + v], pv);
        int gi = NV + NSDV + v;
        if (pv > bmax || (pv == bmax && gi < bidx)) { bmax = pv; bidx = gi; }
    }

    red[tid]  = bmax;
    redi[tid] = bidx;
    __syncthreads();
    for (int o = 128; o > 0; o >>= 1) {
        if (tid < o) {
            float v2 = red[tid + o]; int i2 = redi[tid + o];
            if (v2 > red[tid] || (v2 == red[tid] && i2 < redi[tid])) {
                red[tid] = v2; redi[tid] = i2;
            }
        }
        __syncthreads();
    }
    if (tid == 0) {
        // exact vocab max from the GEMM epilogue
        unsigned long long pk = g_amax[row];
        float vmax  = __expf(unfkey((uint32_t)(pk >> 32))) * scale;
        int   vidx  = (int)(0xFFFFFFFFu - (uint32_t)pk);
        float cmax  = red[0];
        int   cidx  = redi[0];
        int   pred  = (cmax > vmax || (cmax == vmax && cidx < vidx))
                        ? cidx : vidx;
        out[(size_t)MM * NOUT + row] = (float)pred;
    }
}

// ---------------------------------------------------------------------------
extern "C" void kernel_launch(void* const* d_in, const int* in_sizes, int n_in,
                              void* d_out, int out_size) {
    const float* hiddens = (const float*)d_in[0];
    const float* Wp      = (const float*)d_in[1];
    const float* bp      = (const float*)d_in[2];
    const float* Wv      = (const float*)d_in[3];
    const float* bv      = (const float*)d_in[4];
    const float* satt    = (const float*)d_in[5];
    const float* smap    = (const float*)d_in[6];
    const float* tatt    = (const float*)d_in[7];
    const float* tmap    = (const float*)d_in[8];
    float* out = (float*)d_out;

    cudaFuncSetAttribute(gemm_mma_kernel,
                         cudaFuncAttributeMaxDynamicSharedMemorySize, SMEM_GEMM);

    // gemm in launch slot 4 -> gets ncu-captured
    convB_kernel<<<dim3(NV/32, NH/32), dim3(32, 8)>>>(Wv);       // 1
    p_conv_kernel<<<MM/4, 128>>>(hiddens, Wp, bp);               // 2
    prep_idx_kernel<<<8, 256>>>(smap, tmap);                     // 3
    gemm_mma_kernel<<<dim3(NV/BN, MM/BM), 256, SMEM_GEMM>>>(bv); // 4
    finalize_kernel<<<dim3(NQ + 1, MM), 256>>>(satt, tatt, out); // 5
}

// round 16
// speedup vs baseline: 1.2229x; 1.0111x over previous
#include <cuda_runtime.h>
#include <cuda_bf16.h>
#include <cuda_fp16.h>
#include <math.h>
#include <stdint.h>

// Problem constants
#define NB   4
#define NT   512
#define NH   512
#define NV   32000
#define NS   512
#define NSDV 300
#define NTDV 512
#define MM   (NB*NT)              // 2048 rows
#define NOUT (NV+NSDV+NTDV)       // 32812
#define KK   (3*NH)               // 1536 expanded K (Ah|Ah|Al x Bh|Bl|Bh)

// Scratch (static device arrays; no allocation allowed)
__device__ __half g_scoresh[(size_t)MM*NV];       // 131 MB (fp16 scores)
__device__ float g_p[MM*3];
__device__ float g_sumexp[MM];
__device__ unsigned long long g_amax[MM];         // packed exact vocab argmax
__device__ int   g_src_idx[NB*NS];
__device__ int   g_tgt_idx[NB*NT];
__device__ __nv_bfloat16 g_Ap[(size_t)MM*KK];     // 6.3 MB  [m][k']
__device__ __nv_bfloat16 g_Bp[(size_t)NV*KK];     // 98 MB   [n][k'] (K-major)

// ---------------------------------------------------------------------------
__device__ __forceinline__ uint32_t smem_u32(const void* p) {
    uint32_t a;
    asm("{ .reg .u64 t; cvta.to.shared.u64 t, %1; cvt.u32.u64 %0, t; }"
        : "=r"(a) : "l"(p));
    return a;
}
__device__ __forceinline__ void cp_async16(uint32_t dst, const void* src) {
    asm volatile("cp.async.cg.shared.global [%0], [%1], 16;"
                 :: "r"(dst), "l"(src));
}
#define CP_COMMIT() asm volatile("cp.async.commit_group;")
#define CP_WAIT1()  asm volatile("cp.async.wait_group 1;")

__device__ __forceinline__ void ldmx4(uint32_t* r, uint32_t addr) {
    asm volatile("ldmatrix.sync.aligned.m8n8.x4.shared.b16 {%0,%1,%2,%3}, [%4];"
                 : "=r"(r[0]), "=r"(r[1]), "=r"(r[2]), "=r"(r[3]) : "r"(addr));
}
__device__ __forceinline__ void mma16816(float* c, const uint32_t* a,
                                         const uint32_t* b) {
    asm volatile(
        "mma.sync.aligned.m16n8k16.row.col.f32.bf16.bf16.f32 "
        "{%0,%1,%2,%3}, {%4,%5,%6,%7}, {%8,%9}, {%0,%1,%2,%3};"
        : "+f"(c[0]), "+f"(c[1]), "+f"(c[2]), "+f"(c[3])
        : "r"(a[0]), "r"(a[1]), "r"(a[2]), "r"(a[3]), "r"(b[0]), "r"(b[1]));
}

// order-preserving float -> uint key (works for all finite floats)
__device__ __forceinline__ uint32_t fkey(float v) {
    uint32_t b = __float_as_uint(v);
    return b ^ ((b & 0x80000000u) ? 0xFFFFFFFFu : 0x80000000u);
}
__device__ __forceinline__ float unfkey(uint32_t k) {
    uint32_t b = (k & 0x80000000u) ? (k ^ 0x80000000u) : ~k;
    return __uint_as_float(b);
}

// ---------------------------------------------------------------------------
// Merged prologue: one launch, heterogeneous blocks (all 256 threads).
//   blocks [0, 16000)      : convB tiles (Wv transpose -> [Bh|Bl|Bh])
//   blocks [16000, 16256)  : p_conv (gate softmax + A' build + zeroing),
//                            8 rows per block (one warp per row)
//   blocks [16256, 16264)  : prep_idx (one-hot index extraction)
// ---------------------------------------------------------------------------
#define NBLK_CONVB  (NV/32 * NH/32)   // 16000
#define NBLK_PCONV  (MM/8)            // 256
#define NBLK_PREP   8
#define NBLK_PRO    (NBLK_CONVB + NBLK_PCONV + NBLK_PREP)

__global__ __launch_bounds__(256)
void prologue_kernel(const float* __restrict__ Wv,
                     const float* __restrict__ H,
                     const float* __restrict__ Wp,
                     const float* __restrict__ bp,
                     const float* __restrict__ smap,
                     const float* __restrict__ tmap) {
    const int bid = blockIdx.x;
    const int tid = threadIdx.x;

    if (bid < NBLK_CONVB) {
        // ---- convB tile: transpose 32x32 of Wv, hi/lo split ----
        __shared__ float t[32][33];
        const int n0 = (bid % (NV/32)) * 32;
        const int k0 = (bid / (NV/32)) * 32;
        const int tx = tid & 31, ty = tid >> 5;   // (32, 8)
        #pragma unroll
        for (int i = 0; i < 32; i += 8)
            t[ty+i][tx] = Wv[(size_t)(k0 + ty + i) * NV + n0 + tx];
        __syncthreads();
        #pragma unroll
        for (int i = 0; i < 32; i += 8) {
            float v = t[tx][ty+i];                 // k = k0+tx, n = n0+ty+i
            __nv_bfloat16 hi = __float2bfloat16(v);
            __nv_bfloat16 lo = __float2bfloat16(v - __bfloat162float(hi));
            size_t base = (size_t)(n0 + ty + i) * KK + k0 + tx;
            g_Bp[base]        = hi;
            g_Bp[base + NH]   = lo;
            g_Bp[base + 2*NH] = hi;
        }
        return;
    }

    if (bid < NBLK_CONVB + NBLK_PCONV) {
        // ---- p_conv: one warp per row, 8 rows per block ----
        const int warp = tid >> 5;
        const int lane = tid & 31;
        const int row  = (bid - NBLK_CONVB) * 8 + warp;
        const float* h = H + (size_t)row * NH;
        __nv_bfloat16* ap = g_Ap + (size_t)row * KK;
        float s0 = 0.f, s1 = 0.f, s2 = 0.f;
        #pragma unroll
        for (int k = lane; k < NH; k += 32) {
            float hv = h[k];
            __nv_bfloat16 hi = __float2bfloat16(hv);
            __nv_bfloat16 lo = __float2bfloat16(hv - __bfloat162float(hi));
            ap[k]        = hi;
            ap[k + NH]   = hi;
            ap[k + 2*NH] = lo;
            s0 = fmaf(hv, Wp[k*3+0], s0);
            s1 = fmaf(hv, Wp[k*3+1], s1);
            s2 = fmaf(hv, Wp[k*3+2], s2);
        }
        #pragma unroll
        for (int o = 16; o > 0; o >>= 1) {
            s0 += __shfl_down_sync(0xffffffff, s0, o);
            s1 += __shfl_down_sync(0xffffffff, s1, o);
            s2 += __shfl_down_sync(0xffffffff, s2, o);
        }
        if (lane == 0) {
            g_sumexp[row] = 0.f;
            g_amax[row]   = 0ull;
            s0 += bp[0]; s1 += bp[1]; s2 += bp[2];
            float m = fmaxf(s0, fmaxf(s1, s2));
            float e0 = expf(s0 - m), e1 = expf(s1 - m), e2 = expf(s2 - m);
            float inv = 1.0f / (e0 + e1 + e2);
            g_p[row*3+0] = e0 * inv;
            g_p[row*3+1] = e1 * inv;
            g_p[row*3+2] = e2 * inv;
        }
        return;
    }

    // ---- prep_idx ----
    {
        const int i = (bid - NBLK_CONVB - NBLK_PCONV) * 256 + tid;
        if (i >= NB*NS) return;
        {
            const float* r = smap + (size_t)i * NSDV;
            int idx = 0;
            for (int v = 0; v < NSDV; v++) if (r[v] > 0.5f) idx = v;
            g_src_idx[i] = idx;
        }
        {
            const float* r = tmap + (size_t)i * NTDV;
            int idx = 0;
            for (int v = 0; v < NTDV; v++) if (r[v] > 0.5f) idx = v;
            g_tgt_idx[i] = idx;
        }
    }
}

// ---------------------------------------------------------------------------
// mma.sync GEMM (R7 config): 128x128 tiles, BK=64, 3-stage cp.async,
// 8 warps of 32x64, strength-reduced addressing. Epilogue: fp16 score
// store + per-row sumexp + EXACT per-row vocab argmax (packed atomicMax).
// ---------------------------------------------------------------------------
#define BM 128
#define BN 128
#define BK 64
#define NKITER (KK/BK)        // 24
#define STAGE_B 32768         // A tile 16KB + B tile 16KB
#define SMEM_GEMM (3*STAGE_B) // 96 KB

__global__ __launch_bounds__(256, 2)
void gemm_mma_kernel(const float* __restrict__ bias) {
    extern __shared__ char smem[];
    const uint32_t sb = smem_u32(smem);
    const int tid  = threadIdx.x;
    const int w    = tid >> 5;
    const int lane = tid & 31;
    const int bm   = blockIdx.y * BM;    // 16
    const int bn   = blockIdx.x * BN;    // 250
    const int wm   = w & 3;              // warp row (4)
    const int wn   = w >> 2;             // warp col (2)

    float acc[2][8][4];
    #pragma unroll
    for (int i = 0; i < 2; i++)
        #pragma unroll
        for (int j = 0; j < 8; j++)
            #pragma unroll
            for (int q = 0; q < 4; q++) acc[i][j][q] = 0.f;

    // --- strength-reduced loader state ---
    const int lr = tid >> 3;             // 0..31
    const int lc = tid & 7;              // 16B chunk
    const __nv_bfloat16* aptr = g_Ap + (size_t)(bm + lr) * KK + lc * 8;
    const __nv_bfloat16* bptr = g_Bp + (size_t)(bn + lr) * KK + lc * 8;
    const uint32_t sw0 = (uint32_t)lr * 128 + (uint32_t)((lc ^ (lr & 7)) * 16);

#define LOAD_STAGE(s) do {                                                      \
    uint32_t d = sb + (uint32_t)(s) * STAGE_B + sw0;                            \
    _Pragma("unroll")                                                           \
    for (int i = 0; i < 4; i++) {                                               \
        cp_async16(d + i * 4096,         aptr + (size_t)i * 32 * KK);           \
        cp_async16(d + 16384 + i * 4096, bptr + (size_t)i * 32 * KK);           \
    }                                                                           \
    CP_COMMIT();                                                                \
    aptr += BK; bptr += BK;                                                     \
} while (0)

    // --- strength-reduced ldmatrix bases ---
    const uint32_t lnx = (uint32_t)(lane >> 4) * 16;
    uint32_t rp_a[2], rp_b[4];
    #pragma unroll
    for (int i = 0; i < 2; i++) {
        int row = wm * 32 + i * 16 + (lane & 15);
        rp_a[i] = (uint32_t)row * 128 + (lnx ^ (uint32_t)((row & 7) * 16));
    }
    #pragma unroll
    for (int jj = 0; jj < 4; jj++) {
        int row = wn * 64 + jj * 16 + (lane & 15);
        rp_b[jj] = (uint32_t)row * 128 + (lnx ^ (uint32_t)((row & 7) * 16));
    }

    LOAD_STAGE(0);
    LOAD_STAGE(1);

    for (int kt = 0; kt < NKITER; kt++) {
        const int s = kt % 3;
        CP_WAIT1();
        __syncthreads();
        if (kt + 2 < NKITER) LOAD_STAGE((kt + 2) % 3);

        const uint32_t abase = sb + (uint32_t)s * STAGE_B;
        const uint32_t bbase = abase + 16384;
        #pragma unroll
        for (int ks = 0; ks < 4; ks++) {
            const uint32_t kx = (uint32_t)ks << 5;
            uint32_t a[2][4];
            #pragma unroll
            for (int i = 0; i < 2; i++)
                ldmx4(a[i], abase + (rp_a[i] ^ kx));
            uint32_t b[8][2];
            #pragma unroll
            for (int jj = 0; jj < 4; jj++) {
                uint32_t r[4];
                ldmx4(r, bbase + (rp_b[jj] ^ kx));
                b[2*jj][0]   = r[0]; b[2*jj][1]   = r[2];
                b[2*jj+1][0] = r[1]; b[2*jj+1][1] = r[3];
            }
            #pragma unroll
            for (int i = 0; i < 2; i++)
                #pragma unroll
                for (int j = 0; j < 8; j++)
                    mma16816(acc[i][j], a[i], b[j]);
        }
    }

    // epilogue: bias add, fp16 store, per-row sumexp + exact vocab argmax
    #pragma unroll
    for (int i = 0; i < 2; i++) {
        const int row = bm + wm * 32 + i * 16 + (lane >> 2);
        float s0 = 0.f, s1 = 0.f;            // sumexp: rows row, row+8
        float m0 = -INFINITY, m1 = -INFINITY;
        int   c0 = 1, c1 = 1;
        #pragma unroll
        for (int j = 0; j < 8; j++) {
            const int col = bn + wn * 64 + j * 8 + (lane & 3) * 2;
            const float b0 = bias[col], b1 = bias[col + 1];
            float v00 = acc[i][j][0] + b0, v01 = acc[i][j][1] + b1;
            float v10 = acc[i][j][2] + b0, v11 = acc[i][j][3] + b1;
            *(__half2*)(g_scoresh + (size_t)row * NV + col)
                = __floats2half2_rn(v00, v01);
            *(__half2*)(g_scoresh + (size_t)(row + 8) * NV + col)
                = __floats2half2_rn(v10, v11);
            bool nz = (col != 0);
            s0 += (nz ? __expf(v00) : 0.f) + __expf(v01);
            s1 += (nz ? __expf(v10) : 0.f) + __expf(v11);
            if (nz && v00 > m0) { m0 = v00; c0 = col; }
            if (v01 > m0)       { m0 = v01; c0 = col + 1; }
            if (nz && v10 > m1) { m1 = v10; c1 = col; }
            if (v11 > m1)       { m1 = v11; c1 = col + 1; }
        }
        #pragma unroll
        for (int o = 1; o <= 2; o <<= 1) {
            s0 += __shfl_xor_sync(0xffffffff, s0, o);
            s1 += __shfl_xor_sync(0xffffffff, s1, o);
            float mo0 = __shfl_xor_sync(0xffffffff, m0, o);
            int   co0 = __shfl_xor_sync(0xffffffff, c0, o);
            if (mo0 > m0 || (mo0 == m0 && co0 < c0)) { m0 = mo0; c0 = co0; }
            float mo1 = __shfl_xor_sync(0xffffffff, m1, o);
            int   co1 = __shfl_xor_sync(0xffffffff, c1, o);
            if (mo1 > m1 || (mo1 == m1 && co1 < c1)) { m1 = mo1; c1 = co1; }
        }
        if ((lane & 3) == 0) {
            atomicAdd(&g_sumexp[row],     s0);
            atomicAdd(&g_sumexp[row + 8], s1);
            unsigned long long p0 =
                ((unsigned long long)fkey(m0) << 32)
                | (unsigned long long)(0xFFFFFFFFu - (uint32_t)c0);
            unsigned long long p1 =
                ((unsigned long long)fkey(m1) << 32)
                | (unsigned long long)(0xFFFFFFFFu - (uint32_t)c1);
            atomicMax(&g_amax[row],     p0);
            atomicMax(&g_amax[row + 8], p1);
        }
    }
}

// ---------------------------------------------------------------------------
// Finalize: grid (NQ+1, MM). q<NQ: pure-streaming vocab prob write from
// fp16 scores. q==NQ: copy-region scatter + write + final argmax using the
// exact vocab max from the GEMM.
// ---------------------------------------------------------------------------
#define NQ 2
__global__ __launch_bounds__(256)
void finalize_kernel(const float* __restrict__ satt,
                     const float* __restrict__ tatt,
                     float* __restrict__ out) {
    const int row = blockIdx.y;
    const int q   = blockIdx.x;
    const int tid = threadIdx.x;

    const float pg    = g_p[row*3+2];
    const float scale = pg / g_sumexp[row];
    float* orow = out + (size_t)row * NOUT;

    if (q < NQ) {
        // vocab slice: 8 halves (16B) per iteration, pure streaming
        const uint4* s4 = (const uint4*)(g_scoresh + (size_t)row * NV);
        float4* orow4 = (float4*)orow;
        const int i0 = q * (NV/8/NQ);
        for (int i = i0 + tid; i < i0 + NV/8/NQ; i += 256) {
            uint4 u = __ldcs(&s4[i]);
            float2 a0 = __half22float2(*(__half2*)&u.x);
            float2 a1 = __half22float2(*(__half2*)&u.y);
            float2 a2 = __half22float2(*(__half2*)&u.z);
            float2 a3 = __half22float2(*(__half2*)&u.w);
            float4 p0, p1;
            p0.x = __expf(a0.x) * scale;  p0.y = __expf(a0.y) * scale;
            p0.z = __expf(a1.x) * scale;  p0.w = __expf(a1.y) * scale;
            p1.x = __expf(a2.x) * scale;  p1.y = __expf(a2.y) * scale;
            p1.z = __expf(a3.x) * scale;  p1.w = __expf(a3.y) * scale;
            if (i == 0) p0.x = 0.f;      // masked vocab index 0
            __stcs(&orow4[2*i],     p0);
            __stcs(&orow4[2*i + 1], p1);
        }
        return;
    }

    // copy-region block
    __shared__ float red[256];
    __shared__ int   redi[256];
    __shared__ float src_acc[NSDV];
    __shared__ float tgt_acc[NTDV];
    const int b = row / NT;
    const float pcs = g_p[row*3+0];
    const float pct = g_p[row*3+1];

    for (int i = tid; i < NSDV; i += 256) src_acc[i] = 0.f;
    for (int i = tid; i < NTDV; i += 256) tgt_acc[i] = 0.f;
    __syncthreads();
    for (int s = tid; s < NS; s += 256)
        atomicAdd(&src_acc[g_src_idx[b*NS + s]], satt[(size_t)row*NS + s]);
    for (int n = tid; n < NT; n += 256)
        atomicAdd(&tgt_acc[g_tgt_idx[b*NT + n]], tatt[(size_t)row*NTDV + n]);
    __syncthreads();

    float bmax = -1.f;
    int   bidx = NOUT;
    for (int v = tid; v < NSDV; v += 256) {
        float pv = pcs * src_acc[v];
        __stcs(&orow[NV + v], pv);
        int gi = NV + v;
        if (pv > bmax || (pv == bmax && gi < bidx)) { bmax = pv; bidx = gi; }
    }
    for (int v = tid; v < NTDV; v += 256) {
        float pv = pct * tgt_acc[v];
        __stcs(&orow[NV + NSDV + v], pv);
        int gi = NV + NSDV + v;
        if (pv > bmax || (pv == bmax && gi < bidx)) { bmax = pv; bidx = gi; }
    }

    red[tid]  = bmax;
    redi[tid] = bidx;
    __syncthreads();
    for (int o = 128; o > 0; o >>= 1) {
        if (tid < o) {
            float v2 = red[tid + o]; int i2 = redi[tid + o];
            if (v2 > red[tid] || (v2 == red[tid] && i2 < redi[tid])) {
                red[tid] = v2; redi[tid] = i2;
            }
        }
        __syncthreads();
    }
    if (tid == 0) {
        // exact vocab max from the GEMM epilogue
        unsigned long long pk = g_amax[row];
        float vmax  = __expf(unfkey((uint32_t)(pk >> 32))) * scale;
        int   vidx  = (int)(0xFFFFFFFFu - (uint32_t)pk);
        float cmax  = red[0];
        int   cidx  = redi[0];
        int   pred  = (cmax > vmax || (cmax == vmax && cidx < vidx))
                        ? cidx : vidx;
        out[(size_t)MM * NOUT + row] = (float)pred;
    }
}

// ---------------------------------------------------------------------------
extern "C" void kernel_launch(void* const* d_in, const int* in_sizes, int n_in,
                              void* d_out, int out_size) {
    const float* hiddens = (const float*)d_in[0];
    const float* Wp      = (const float*)d_in[1];
    const float* bp      = (const float*)d_in[2];
    const float* Wv      = (const float*)d_in[3];
    const float* bv      = (const float*)d_in[4];
    const float* satt    = (const float*)d_in[5];
    const float* smap    = (const float*)d_in[6];
    const float* tatt    = (const float*)d_in[7];
    const float* tmap    = (const float*)d_in[8];
    float* out = (float*)d_out;

    cudaFuncSetAttribute(gemm_mma_kernel,
                         cudaFuncAttributeMaxDynamicSharedMemorySize, SMEM_GEMM);

    prologue_kernel<<<NBLK_PRO, 256>>>(Wv, hiddens, Wp, bp, smap, tmap); // 1
    gemm_mma_kernel<<<dim3(NV/BN, MM/BM), 256, SMEM_GEMM>>>(bv);         // 2
    finalize_kernel<<<dim3(NQ + 1, MM), 256>>>(satt, tatt, out);         // 3
}